// round 6
// baseline (speedup 1.0000x reference)
#include <cuda_runtime.h>
#include <cuda_bf16.h>
#include <cstdint>
#include <math.h>

// ---------------- static device scratch (no cudaMalloc allowed) ----------------
__device__ float g_xg[16384ull * 3072];   // (B*T, 3H) gate pre-activations, row = b*256+t
__device__ float g_wt[1024 * 1024];       // W_in transposed: [d][h]
__device__ float g_wcomb[3072 * 1024];    // W_ih @ W_in : [g][d]
__device__ float g_bcomb[3072];           // W_ih @ b_in + b_ih
__device__ float g_h[2 * 64 * 1024];      // ping-pong hidden state
__device__ unsigned g_cnt = 0;            // grid barrier arrive counter
__device__ unsigned g_gen = 0;            // grid barrier generation

// ---------------- helpers ----------------
__device__ __forceinline__ void split_bf16(float x, __nv_bfloat16& hi, __nv_bfloat16& lo) {
    hi = __float2bfloat16(x);
    lo = __float2bfloat16(x - __bfloat162float(hi));
}

__device__ __forceinline__ uint32_t ld_pair(const __nv_bfloat16* p) {
    return *reinterpret_cast<const uint32_t*>(p);
}

__device__ __forceinline__ void mma16816(float* c, const uint32_t* a, const uint32_t* b) {
    asm volatile(
        "mma.sync.aligned.m16n8k16.row.col.f32.bf16.bf16.f32 "
        "{%0,%1,%2,%3}, {%4,%5,%6,%7}, {%8,%9}, {%0,%1,%2,%3};\n"
        : "+f"(c[0]), "+f"(c[1]), "+f"(c[2]), "+f"(c[3])
        : "r"(a[0]), "r"(a[1]), "r"(a[2]), "r"(a[3]), "r"(b[0]), "r"(b[1]));
}

// =====================================================================
// Transpose 1024x1024: out[d][h] = in[h][d]
// =====================================================================
__global__ void transpose_k(const float* __restrict__ in, float* __restrict__ out) {
    __shared__ float t[32][33];
    int x = blockIdx.x * 32 + threadIdx.x;
    int y = blockIdx.y * 32 + threadIdx.y;
    #pragma unroll
    for (int i = 0; i < 32; i += 8)
        t[threadIdx.y + i][threadIdx.x] = in[(size_t)(y + i) * 1024 + x];
    __syncthreads();
    int xo = blockIdx.y * 32 + threadIdx.x;
    int yo = blockIdx.x * 32 + threadIdx.y;
    #pragma unroll
    for (int i = 0; i < 32; i += 8)
        out[(size_t)(yo + i) * 1024 + xo] = t[threadIdx.x][threadIdx.y + i];
}

// =====================================================================
// b_comb[g] = b_ih[g] + sum_h W_ih[g,h] * b_in[h]
// =====================================================================
__global__ void bcomb_k(const float* __restrict__ W_ih, const float* __restrict__ b_in,
                        const float* __restrict__ b_ih, float* __restrict__ out) {
    int g = blockIdx.x * blockDim.x + threadIdx.x;
    if (g < 3072) {
        float s = b_ih[g];
        const float* row = W_ih + (size_t)g * 1024;
        for (int h = 0; h < 1024; h++) s += row[h] * b_in[h];
        out[g] = s;
    }
}

__global__ void copy_k(const float* __restrict__ s, float* __restrict__ d, int n) {
    int i = blockIdx.x * blockDim.x + threadIdx.x;
    if (i < n) d[i] = s[i];
}

// =====================================================================
// Generic NT GEMM: C[M,N] = A[M,K] @ B[N,K]^T (+ bias[N])
// bf16 hi/lo 3-product split, fp32 accumulate.
// Block tile 128x128, BK=32, 256 threads = 8 warps (4 m-warps x 2 n-warps).
// Dynamic smem, DOUBLE-BUFFERED, register prefetch, 1 sync per k-tile.
// (At HBM roofline per ncu R4 — left unchanged this round.)
// =====================================================================
#define GTILE 5120   // 128*40 elems per array
#define GEMM_SMEM (2 * 4 * GTILE * 2)   // bytes = 81920

__global__ __launch_bounds__(256, 1)
void gemm3x_k(const float* __restrict__ A, const float* __restrict__ B,
              const float* __restrict__ bias, float* __restrict__ C,
              int M, int N, int K)
{
    extern __shared__ __nv_bfloat16 gsm[];

    const int tid = threadIdx.x;
    const int lane = tid & 31;
    const int warp = tid >> 5;
    const int g = lane >> 2;      // group id 0..7
    const int tig = lane & 3;     // thread in group
    const int m0w = (warp >> 1) * 32;
    const int n0w = (warp & 1) * 64;

    const int mBase = blockIdx.y * 128;
    const int nBase = blockIdx.x * 128;

    float acc[2][8][4];
    #pragma unroll
    for (int mt = 0; mt < 2; mt++)
        #pragma unroll
        for (int nt = 0; nt < 8; nt++)
            #pragma unroll
            for (int i = 0; i < 4; i++) acc[mt][nt][i] = 0.f;

    const int nKT = K >> 5;
    float4 pa[4], pb[4];

    // prologue: prefetch tile 0 into regs
    #pragma unroll
    for (int it = 0; it < 4; it++) {
        int id = tid + it * 256;
        int r = id >> 3;
        int kq = (id & 7) << 2;
        int gr = mBase + r;
        pa[it] = (gr < M) ? *reinterpret_cast<const float4*>(A + (size_t)gr * K + kq)
                          : make_float4(0.f, 0.f, 0.f, 0.f);
        pb[it] = *reinterpret_cast<const float4*>(B + (size_t)(nBase + r) * K + kq);
    }

    for (int kt = 0; kt < nKT; kt++) {
        __nv_bfloat16* base = gsm + (size_t)(kt & 1) * (4 * GTILE);
        __nv_bfloat16* sAhi = base;
        __nv_bfloat16* sAlo = base + GTILE;
        __nv_bfloat16* sBhi = base + 2 * GTILE;
        __nv_bfloat16* sBlo = base + 3 * GTILE;

        // store prefetched regs -> smem (split)
        #pragma unroll
        for (int it = 0; it < 4; it++) {
            int id = tid + it * 256;
            int r = id >> 3;
            int kq = (id & 7) << 2;
            __nv_bfloat16 h, l;
            split_bf16(pa[it].x, h, l); sAhi[r * 40 + kq + 0] = h; sAlo[r * 40 + kq + 0] = l;
            split_bf16(pa[it].y, h, l); sAhi[r * 40 + kq + 1] = h; sAlo[r * 40 + kq + 1] = l;
            split_bf16(pa[it].z, h, l); sAhi[r * 40 + kq + 2] = h; sAlo[r * 40 + kq + 2] = l;
            split_bf16(pa[it].w, h, l); sAhi[r * 40 + kq + 3] = h; sAlo[r * 40 + kq + 3] = l;
            split_bf16(pb[it].x, h, l); sBhi[r * 40 + kq + 0] = h; sBlo[r * 40 + kq + 0] = l;
            split_bf16(pb[it].y, h, l); sBhi[r * 40 + kq + 1] = h; sBlo[r * 40 + kq + 1] = l;
            split_bf16(pb[it].z, h, l); sBhi[r * 40 + kq + 2] = h; sBlo[r * 40 + kq + 2] = l;
            split_bf16(pb[it].w, h, l); sBhi[r * 40 + kq + 3] = h; sBlo[r * 40 + kq + 3] = l;
        }
        __syncthreads();

        // prefetch next tile under this tile's MMAs
        if (kt + 1 < nKT) {
            int k0 = (kt + 1) << 5;
            #pragma unroll
            for (int it = 0; it < 4; it++) {
                int id = tid + it * 256;
                int r = id >> 3;
                int kq = (id & 7) << 2;
                int gr = mBase + r;
                pa[it] = (gr < M) ? *reinterpret_cast<const float4*>(A + (size_t)gr * K + k0 + kq)
                                  : make_float4(0.f, 0.f, 0.f, 0.f);
                pb[it] = *reinterpret_cast<const float4*>(B + (size_t)(nBase + r) * K + k0 + kq);
            }
        }

        #pragma unroll
        for (int kk = 0; kk < 32; kk += 16) {
            uint32_t Ah[2][4], Al[2][4], Bh[8][2], Bl[8][2];
            #pragma unroll
            for (int mt = 0; mt < 2; mt++) {
                int r0 = m0w + 16 * mt;
                Ah[mt][0] = ld_pair(&sAhi[(r0 + g) * 40 + kk + 2 * tig]);
                Ah[mt][1] = ld_pair(&sAhi[(r0 + g + 8) * 40 + kk + 2 * tig]);
                Ah[mt][2] = ld_pair(&sAhi[(r0 + g) * 40 + kk + 2 * tig + 8]);
                Ah[mt][3] = ld_pair(&sAhi[(r0 + g + 8) * 40 + kk + 2 * tig + 8]);
                Al[mt][0] = ld_pair(&sAlo[(r0 + g) * 40 + kk + 2 * tig]);
                Al[mt][1] = ld_pair(&sAlo[(r0 + g + 8) * 40 + kk + 2 * tig]);
                Al[mt][2] = ld_pair(&sAlo[(r0 + g) * 40 + kk + 2 * tig + 8]);
                Al[mt][3] = ld_pair(&sAlo[(r0 + g + 8) * 40 + kk + 2 * tig + 8]);
            }
            #pragma unroll
            for (int nt = 0; nt < 8; nt++) {
                int r0 = n0w + 8 * nt + g;
                Bh[nt][0] = ld_pair(&sBhi[r0 * 40 + kk + 2 * tig]);
                Bh[nt][1] = ld_pair(&sBhi[r0 * 40 + kk + 2 * tig + 8]);
                Bl[nt][0] = ld_pair(&sBlo[r0 * 40 + kk + 2 * tig]);
                Bl[nt][1] = ld_pair(&sBlo[r0 * 40 + kk + 2 * tig + 8]);
            }
            #pragma unroll
            for (int mt = 0; mt < 2; mt++)
                #pragma unroll
                for (int nt = 0; nt < 8; nt++) {
                    mma16816(acc[mt][nt], Ah[mt], Bh[nt]);
                    mma16816(acc[mt][nt], Ah[mt], Bl[nt]);
                    mma16816(acc[mt][nt], Al[mt], Bh[nt]);
                }
        }
        // no trailing sync: next iter writes the OTHER buffer, whose readers
        // all passed this iter's __syncthreads before issuing those reads.
    }

    // epilogue
    #pragma unroll
    for (int mt = 0; mt < 2; mt++) {
        #pragma unroll
        for (int nt = 0; nt < 8; nt++) {
            int col = nBase + n0w + 8 * nt + 2 * tig;
            float b0 = bias ? bias[col] : 0.f;
            float b1 = bias ? bias[col + 1] : 0.f;
            int r0 = mBase + m0w + 16 * mt + g;
            if (r0 < M) {
                C[(size_t)r0 * N + col]     = acc[mt][nt][0] + b0;
                C[(size_t)r0 * N + col + 1] = acc[mt][nt][1] + b1;
            }
            if (r0 + 8 < M) {
                C[(size_t)(r0 + 8) * N + col]     = acc[mt][nt][2] + b0;
                C[(size_t)(r0 + 8) * N + col + 1] = acc[mt][nt][3] + b1;
            }
        }
    }
}

// =====================================================================
// Persistent GRU recurrence kernel.
// grid = 64 blocks x 256 threads, ALL co-resident (1 CTA/SM).
// CHANGE (R5): 18 independent accumulator chains per warp —
// acc[kk-parity][split-product][nt] — chain depth per step drops 192 -> 32.
// =====================================================================
#define WSTR 1032                       // W smem row stride (bank conflict-free)
#define ASTR 40                         // A smem row stride
#define GRU_SMEM ((2 * 48 * WSTR + 2 * 2 * 64 * ASTR) * 2)   // 218624 bytes
#define NBLK 64

__device__ __forceinline__ void gridbar64() {
    __syncthreads();
    if (threadIdx.x == 0) {
        __threadfence();                       // release (cumulative): publish block's h writes
        unsigned gen = atomicAdd(&g_gen, 0u);  // read generation BEFORE arriving
        if (atomicAdd(&g_cnt, 1u) == NBLK - 1u) {
            atomicExch(&g_cnt, 0u);
            __threadfence();
            atomicAdd(&g_gen, 1u);
        } else {
            while (atomicAdd(&g_gen, 0u) == gen) { }
        }
        __threadfence();                       // acquire
    }
    __syncthreads();
}

__global__ __launch_bounds__(256, 1)
void gru_persist_k(const float* __restrict__ xg, const float* __restrict__ W_hh,
                   const float* __restrict__ b_hh, const float* __restrict__ hidden,
                   float* __restrict__ hbuf)
{
    extern __shared__ __nv_bfloat16 dsm[];
    __nv_bfloat16* sWhi = dsm;                       // [48][WSTR]
    __nv_bfloat16* sWlo = dsm + 48 * WSTR;
    __nv_bfloat16* sAb  = dsm + 2 * 48 * WSTR;       // [2 buf][hi|lo][64][ASTR]
    float* shg = reinterpret_cast<float*>(sAb);      // [64][49] (reuses A buffers)
    __shared__ float sbh[48];

    const int tid = threadIdx.x;
    const int lane = tid & 31;
    const int warp = tid >> 5;
    const int g = lane >> 2;
    const int tig = lane & 3;
    const int m0w = (warp >> 1) * 16;   // 4 m-warps (batch rows)
    const int n0w = (warp & 1) * 24;    // 2 n-warps, 3 n8-tiles each
    const int j0 = blockIdx.x * 16;

    // ---- stage W_hh slice (48 rows x 1024) into smem, hi/lo ----
    for (int idx = tid; idx < 48 * 256; idx += 256) {
        int r = idx >> 8;                 // 0..47
        int c4 = (idx & 255) << 2;        // 0..1020
        int grow = (r >> 4) * 1024 + j0 + (r & 15);
        float4 v = *reinterpret_cast<const float4*>(W_hh + (size_t)grow * 1024 + c4);
        __nv_bfloat16 h, l;
        split_bf16(v.x, h, l); sWhi[r * WSTR + c4 + 0] = h; sWlo[r * WSTR + c4 + 0] = l;
        split_bf16(v.y, h, l); sWhi[r * WSTR + c4 + 1] = h; sWlo[r * WSTR + c4 + 1] = l;
        split_bf16(v.z, h, l); sWhi[r * WSTR + c4 + 2] = h; sWlo[r * WSTR + c4 + 2] = l;
        split_bf16(v.w, h, l); sWhi[r * WSTR + c4 + 3] = h; sWlo[r * WSTR + c4 + 3] = l;
    }
    if (tid < 48) sbh[tid] = b_hh[(tid >> 4) * 1024 + j0 + (tid & 15)];
    __syncthreads();

    const int b_  = tid >> 2;             // epilogue: batch row
    const int uu0 = (tid & 3) << 2;       // epilogue: first of 4 units
    const int ar0 = tid >> 3;             // staging row (0..31), +32 for 2nd
    const int akq = (tid & 7) << 2;       // staging col quad

    for (int t = 0; t < 256; t++) {
        const float* hsrc = (t == 0) ? hidden : (hbuf + (size_t)(t & 1) * 65536);
        float* hdst = hbuf + (size_t)((t + 1) & 1) * 65536;

        // prefetch epilogue operands (independent of MMA chain)
        const float* xrow = xg + (size_t)(b_ * 256 + t) * 3072 + j0 + uu0;
        float4 xr4 = *reinterpret_cast<const float4*>(xrow);
        float4 xz4 = *reinterpret_cast<const float4*>(xrow + 1024);
        float4 xn4 = *reinterpret_cast<const float4*>(xrow + 2048);
        float4 ho4 = *reinterpret_cast<const float4*>(hsrc + (size_t)b_ * 1024 + j0 + uu0);

        // 18 INDEPENDENT accumulator chains: [kk-parity][split][nt][4]
        float acc[2][3][3][4];
        #pragma unroll
        for (int ki = 0; ki < 2; ki++)
            #pragma unroll
            for (int s = 0; s < 3; s++)
                #pragma unroll
                for (int nt = 0; nt < 3; nt++)
                    #pragma unroll
                    for (int i = 0; i < 4; i++) acc[ki][s][nt][i] = 0.f;

        // prologue: prefetch h tile 0
        float4 pv0 = *reinterpret_cast<const float4*>(hsrc + (size_t)ar0 * 1024 + akq);
        float4 pv1 = *reinterpret_cast<const float4*>(hsrc + (size_t)(ar0 + 32) * 1024 + akq);

        for (int kt = 0; kt < 32; kt++) {
            __nv_bfloat16* sAhi = sAb + (size_t)(kt & 1) * (2 * 64 * ASTR);
            __nv_bfloat16* sAlo = sAhi + 64 * ASTR;

            {
                __nv_bfloat16 h, l;
                split_bf16(pv0.x, h, l); sAhi[ar0 * ASTR + akq + 0] = h; sAlo[ar0 * ASTR + akq + 0] = l;
                split_bf16(pv0.y, h, l); sAhi[ar0 * ASTR + akq + 1] = h; sAlo[ar0 * ASTR + akq + 1] = l;
                split_bf16(pv0.z, h, l); sAhi[ar0 * ASTR + akq + 2] = h; sAlo[ar0 * ASTR + akq + 2] = l;
                split_bf16(pv0.w, h, l); sAhi[ar0 * ASTR + akq + 3] = h; sAlo[ar0 * ASTR + akq + 3] = l;
                split_bf16(pv1.x, h, l); sAhi[(ar0 + 32) * ASTR + akq + 0] = h; sAlo[(ar0 + 32) * ASTR + akq + 0] = l;
                split_bf16(pv1.y, h, l); sAhi[(ar0 + 32) * ASTR + akq + 1] = h; sAlo[(ar0 + 32) * ASTR + akq + 1] = l;
                split_bf16(pv1.z, h, l); sAhi[(ar0 + 32) * ASTR + akq + 2] = h; sAlo[(ar0 + 32) * ASTR + akq + 2] = l;
                split_bf16(pv1.w, h, l); sAhi[(ar0 + 32) * ASTR + akq + 3] = h; sAlo[(ar0 + 32) * ASTR + akq + 3] = l;
            }
            __syncthreads();

            if (kt < 31) {
                int k0 = (kt + 1) << 5;
                pv0 = *reinterpret_cast<const float4*>(hsrc + (size_t)ar0 * 1024 + k0 + akq);
                pv1 = *reinterpret_cast<const float4*>(hsrc + (size_t)(ar0 + 32) * 1024 + k0 + akq);
            }

            const int kb = kt << 5;
            #pragma unroll
            for (int ki = 0; ki < 2; ki++) {
                const int kk = ki << 4;
                uint32_t Ah[4], Al[4];
                Ah[0] = ld_pair(&sAhi[(m0w + g) * ASTR + kk + 2 * tig]);
                Ah[1] = ld_pair(&sAhi[(m0w + g + 8) * ASTR + kk + 2 * tig]);
                Ah[2] = ld_pair(&sAhi[(m0w + g) * ASTR + kk + 2 * tig + 8]);
                Ah[3] = ld_pair(&sAhi[(m0w + g + 8) * ASTR + kk + 2 * tig + 8]);
                Al[0] = ld_pair(&sAlo[(m0w + g) * ASTR + kk + 2 * tig]);
                Al[1] = ld_pair(&sAlo[(m0w + g + 8) * ASTR + kk + 2 * tig]);
                Al[2] = ld_pair(&sAlo[(m0w + g) * ASTR + kk + 2 * tig + 8]);
                Al[3] = ld_pair(&sAlo[(m0w + g + 8) * ASTR + kk + 2 * tig + 8]);
                #pragma unroll
                for (int nt = 0; nt < 3; nt++) {
                    int r0 = n0w + 8 * nt + g;
                    uint32_t Bh[2], Bl[2];
                    Bh[0] = ld_pair(&sWhi[r0 * WSTR + kb + kk + 2 * tig]);
                    Bh[1] = ld_pair(&sWhi[r0 * WSTR + kb + kk + 2 * tig + 8]);
                    Bl[0] = ld_pair(&sWlo[r0 * WSTR + kb + kk + 2 * tig]);
                    Bl[1] = ld_pair(&sWlo[r0 * WSTR + kb + kk + 2 * tig + 8]);
                    mma16816(acc[ki][0][nt], Ah, Bh);   // independent chains:
                    mma16816(acc[ki][1][nt], Ah, Bl);   // each (ki, split, nt)
                    mma16816(acc[ki][2][nt], Al, Bh);   // has its own accumulator
                }
            }
            // single sync per tile (double-buffered)
        }

        __syncthreads();   // all MMAs done before shg aliases the A buffers

        // reduce 6 partial sets per nt, then write hg tile to smem
        #pragma unroll
        for (int nt = 0; nt < 3; nt++) {
            float red[4];
            #pragma unroll
            for (int i = 0; i < 4; i++)
                red[i] = ((acc[0][0][nt][i] + acc[0][1][nt][i]) + (acc[0][2][nt][i] + acc[1][0][nt][i]))
                       + (acc[1][1][nt][i] + acc[1][2][nt][i]);
            int col = n0w + 8 * nt + 2 * tig;
            shg[(m0w + g) * 49 + col]         = red[0];
            shg[(m0w + g) * 49 + col + 1]     = red[1];
            shg[(m0w + g + 8) * 49 + col]     = red[2];
            shg[(m0w + g + 8) * 49 + col + 1] = red[3];
        }
        __syncthreads();

        // fused gates: 4 units per thread
        {
            const float* xrp = reinterpret_cast<const float*>(&xr4);
            const float* xzp = reinterpret_cast<const float*>(&xz4);
            const float* xnp = reinterpret_cast<const float*>(&xn4);
            const float* hop = reinterpret_cast<const float*>(&ho4);
            float4 res;
            float* rp = reinterpret_cast<float*>(&res);
            #pragma unroll
            for (int i = 0; i < 4; i++) {
                int uu = uu0 + i;
                float hr = shg[b_ * 49 + uu] + sbh[uu];
                float hz = shg[b_ * 49 + 16 + uu] + sbh[16 + uu];
                float hn = shg[b_ * 49 + 32 + uu] + sbh[32 + uu];
                float r = 1.f / (1.f + expf(-(xrp[i] + hr)));
                float z = 1.f / (1.f + expf(-(xzp[i] + hz)));
                float n = tanhf(xnp[i] + r * hn);
                rp[i] = (1.f - z) * n + z * hop[i];
            }
            *reinterpret_cast<float4*>(hdst + (size_t)b_ * 1024 + j0 + uu0) = res;
        }

        gridbar64();
    }
}

// =====================================================================
// launch
// =====================================================================
extern "C" void kernel_launch(void* const* d_in, const int* in_sizes, int n_in,
                              void* d_out, int out_size)
{
    const float* inp    = (const float*)d_in[0];  // (64,256,1024)
    const float* hidden = (const float*)d_in[1];  // (1,64,1024)
    const float* W_in   = (const float*)d_in[2];  // (1024,1024)
    const float* b_in   = (const float*)d_in[3];  // (1024)
    const float* W_ih   = (const float*)d_in[4];  // (3072,1024)
    const float* b_ih   = (const float*)d_in[5];  // (3072)
    const float* W_hh   = (const float*)d_in[6];  // (3072,1024)
    const float* b_hh   = (const float*)d_in[7];  // (3072)
    const float* W_out  = (const float*)d_in[8];  // (1024,1024)
    const float* b_out  = (const float*)d_in[9];  // (1024)
    float* out = (float*)d_out;

    float* xg    = g_xg;
    float* wt    = g_wt;
    float* wcomb = g_wcomb;
    float* bcomb = g_bcomb;
    float* hbuf  = g_h;

    cudaFuncSetAttribute(gemm3x_k, cudaFuncAttributeMaxDynamicSharedMemorySize, GEMM_SMEM);
    cudaFuncSetAttribute(gru_persist_k, cudaFuncAttributeMaxDynamicSharedMemorySize, GRU_SMEM);

    // W_in^T
    transpose_k<<<dim3(32, 32), dim3(32, 8)>>>(W_in, wt);
    // b_comb
    bcomb_k<<<12, 256>>>(W_ih, b_in, b_ih, bcomb);
    // W_comb = W_ih @ W_in  (M=3072, N=1024, K=1024)
    gemm3x_k<<<dim3(8, 24), 256, GEMM_SMEM>>>(W_ih, wt, nullptr, wcomb, 3072, 1024, 1024);
    // x_gates = inp @ W_comb^T + b_comb  (M=16384, N=3072, K=1024)
    gemm3x_k<<<dim3(24, 128), 256, GEMM_SMEM>>>(inp, wcomb, bcomb, xg, 16384, 3072, 1024);
    // full recurrence in ONE persistent kernel (final h lands in hbuf[0])
    gru_persist_k<<<NBLK, 256, GRU_SMEM>>>(xg, W_hh, b_hh, hidden, hbuf);
    // out_last = h_T @ W_out^T + b_out  (M=64, N=1024, K=1024)
    gemm3x_k<<<dim3(8, 1), 256, GEMM_SMEM>>>(hbuf, W_out, b_out, out, 64, 1024, 1024);
    // hidden_out = h_T
    copy_k<<<256, 256>>>(hbuf, out + 65536, 65536);
}

// round 8
// speedup vs baseline: 1.7771x; 1.7771x over previous
#include <cuda_runtime.h>
#include <cstdint>
#include <math.h>

#define NBLK2 128

__device__ float g_xg[16384ull * 3072];
__device__ float g_wt[1024 * 1024];
__device__ float g_wcomb[3072 * 1024];
__device__ float g_bcomb[3072];
__device__ float g_hfin[64 * 1024];
__device__ float g_ht[2][1024 * 64];      // transposed hidden ping-pong: [k][b]
__device__ unsigned g_cnt = 0, g_gen = 0;

// ---------------- f32x2 helpers ----------------
__device__ __forceinline__ uint64_t pack2(float lo, float hi) {
    uint64_t r;
    asm("mov.b64 %0, {%1, %2};" : "=l"(r) : "f"(lo), "f"(hi));
    return r;
}
__device__ __forceinline__ void unpack2(uint64_t v, float& lo, float& hi) {
    asm("mov.b64 {%0, %1}, %2;" : "=f"(lo), "=f"(hi) : "l"(v));
}
__device__ __forceinline__ uint64_t ffma2(uint64_t a, uint64_t b, uint64_t c) {
    uint64_t d;
    asm("fma.rn.f32x2 %0, %1, %2, %3;" : "=l"(d) : "l"(a), "l"(b), "l"(c));
    return d;
}

// ---------------- prep kernels ----------------
__global__ void transpose_k(const float* __restrict__ in, float* __restrict__ out) {
    __shared__ float t[32][33];
    int x = blockIdx.x * 32 + threadIdx.x, y = blockIdx.y * 32 + threadIdx.y;
    #pragma unroll
    for (int i = 0; i < 32; i += 8) t[threadIdx.y + i][threadIdx.x] = in[(size_t)(y + i) * 1024 + x];
    __syncthreads();
    int xo = blockIdx.y * 32 + threadIdx.x, yo = blockIdx.x * 32 + threadIdx.y;
    #pragma unroll
    for (int i = 0; i < 32; i += 8) out[(size_t)(yo + i) * 1024 + xo] = t[threadIdx.x][threadIdx.y + i];
}
__global__ void bcomb_k(const float* __restrict__ W, const float* __restrict__ b_in,
                        const float* __restrict__ b_ih, float* __restrict__ out) {
    int g = blockIdx.x * blockDim.x + threadIdx.x;
    if (g < 3072) {
        float s = b_ih[g];
        const float* row = W + (size_t)g * 1024;
        for (int h = 0; h < 1024; h++) s += row[h] * b_in[h];
        out[g] = s;
    }
}
__global__ void copy_k(const float* __restrict__ s, float* __restrict__ d, int n) {
    int i = blockIdx.x * blockDim.x + threadIdx.x;
    if (i < n) d[i] = s[i];
}

// =====================================================================
// SIMT fp32 NT GEMM via fma.rn.f32x2: C[M,N] = A[M,K] @ B[N,K]^T (+bias)
// 128x128 block tile, BK=16, 256 threads (16x16), 8x8 per thread.
// Double-buffered static smem. N%128==0, K%16==0; M guarded.
// =====================================================================
__global__ __launch_bounds__(256, 1)
void gemm_f2_k(const float* __restrict__ A, const float* __restrict__ B,
               const float* __restrict__ bias, float* __restrict__ C,
               int M, int N, int K)
{
    __shared__ float As[2][16][132];
    __shared__ float Bs[2][16][132];
    const int tid = threadIdx.x, tx = tid & 15, ty = tid >> 4;
    const int mB = blockIdx.y * 128, nB = blockIdx.x * 128;

    uint64_t acc[8][4];
    #pragma unroll
    for (int i = 0; i < 8; i++)
        #pragma unroll
        for (int j = 0; j < 4; j++) acc[i][j] = 0ull;

    const int NKT = K >> 4;
    float4 ra[2], rb[2];
    int rr[2], kk4[2];
    #pragma unroll
    for (int i = 0; i < 2; i++) {
        int id = tid + i * 256;
        rr[i] = id >> 2;
        kk4[i] = (id & 3) << 2;
    }

    // prologue: load tile 0 and store to buf 0
    #pragma unroll
    for (int i = 0; i < 2; i++) {
        ra[i] = (mB + rr[i] < M) ? *reinterpret_cast<const float4*>(A + (size_t)(mB + rr[i]) * K + kk4[i])
                                 : make_float4(0.f, 0.f, 0.f, 0.f);
        rb[i] = *reinterpret_cast<const float4*>(B + (size_t)(nB + rr[i]) * K + kk4[i]);
    }
    #pragma unroll
    for (int i = 0; i < 2; i++) {
        const float* pa = &ra[i].x;
        const float* pb = &rb[i].x;
        #pragma unroll
        for (int j = 0; j < 4; j++) {
            As[0][kk4[i] + j][rr[i]] = pa[j];
            Bs[0][kk4[i] + j][rr[i]] = pb[j];
        }
    }
    __syncthreads();

    for (int kt = 0; kt < NKT; kt++) {
        const int b = kt & 1;
        // prefetch next tile
        if (kt + 1 < NKT) {
            int k0 = (kt + 1) << 4;
            #pragma unroll
            for (int i = 0; i < 2; i++) {
                ra[i] = (mB + rr[i] < M) ? *reinterpret_cast<const float4*>(A + (size_t)(mB + rr[i]) * K + k0 + kk4[i])
                                         : make_float4(0.f, 0.f, 0.f, 0.f);
                rb[i] = *reinterpret_cast<const float4*>(B + (size_t)(nB + rr[i]) * K + k0 + kk4[i]);
            }
        }
        // compute on buf b
        #pragma unroll
        for (int k = 0; k < 16; k++) {
            float4 a0 = *reinterpret_cast<const float4*>(&As[b][k][ty * 4]);
            float4 a1 = *reinterpret_cast<const float4*>(&As[b][k][64 + ty * 4]);
            float4 b0 = *reinterpret_cast<const float4*>(&Bs[b][k][tx * 4]);
            float4 b1 = *reinterpret_cast<const float4*>(&Bs[b][k][64 + tx * 4]);
            uint64_t bp[4] = { pack2(b0.x, b0.y), pack2(b0.z, b0.w),
                               pack2(b1.x, b1.y), pack2(b1.z, b1.w) };
            float av[8] = { a0.x, a0.y, a0.z, a0.w, a1.x, a1.y, a1.z, a1.w };
            #pragma unroll
            for (int i = 0; i < 8; i++) {
                uint64_t ad = pack2(av[i], av[i]);
                #pragma unroll
                for (int j = 0; j < 4; j++) acc[i][j] = ffma2(ad, bp[j], acc[i][j]);
            }
        }
        // store next tile into other buffer
        if (kt + 1 < NKT) {
            int nb = b ^ 1;
            #pragma unroll
            for (int i = 0; i < 2; i++) {
                const float* pa = &ra[i].x;
                const float* pb = &rb[i].x;
                #pragma unroll
                for (int j = 0; j < 4; j++) {
                    As[nb][kk4[i] + j][rr[i]] = pa[j];
                    Bs[nb][kk4[i] + j][rr[i]] = pb[j];
                }
            }
            __syncthreads();
        }
    }

    // epilogue
    #pragma unroll
    for (int i = 0; i < 8; i++) {
        int row = mB + ((i < 4) ? ty * 4 + i : 64 + ty * 4 + (i - 4));
        if (row < M) {
            float* cr = C + (size_t)row * N + nB;
            #pragma unroll
            for (int j = 0; j < 4; j++) {
                int c = (j < 2) ? tx * 4 + 2 * j : 64 + tx * 4 + 2 * (j - 2);
                float lo, hi;
                unpack2(acc[i][j], lo, hi);
                float v0 = bias ? bias[nB + c] : 0.f;
                float v1 = bias ? bias[nB + c + 1] : 0.f;
                cr[c] = lo + v0;
                cr[c + 1] = hi + v1;
            }
        }
    }
}

// =====================================================================
// Persistent SIMT GRU recurrence (fp32, f32x2).
// 128 blocks x 256 threads, 1 CTA/SM. Block owns 8 units (24 W rows).
// Wt[k][r] resident in smem (96KB, transposed). h in global transposed
// ping-pong ht[k][b] for coalesced loads. Thread = (rg=tid>>6, b=tid&63):
// 3 row-pairs per thread, 1024-k dot via 3 FFMA2/k (W via LDS.64 broadcast).
// =====================================================================
#define GRU_SMEM (1024 * 24 * 4 + 64 * 26 * 4)   // 104960

__device__ __forceinline__ void gridbar() {
    __syncthreads();
    if (threadIdx.x == 0) {
        __threadfence();
        unsigned gen = atomicAdd(&g_gen, 0u);
        if (atomicAdd(&g_cnt, 1u) == NBLK2 - 1u) {
            atomicExch(&g_cnt, 0u);
            __threadfence();
            atomicAdd(&g_gen, 1u);
        } else {
            while (atomicAdd(&g_gen, 0u) == gen) { }
        }
        __threadfence();
    }
    __syncthreads();
}

__global__ __launch_bounds__(256, 1)
void gru_f2_k(const float* __restrict__ xg, const float* __restrict__ W_hh,
              const float* __restrict__ b_hh, const float* __restrict__ hidden,
              float* __restrict__ hfin)
{
    extern __shared__ float sm[];
    float* Wt = sm;                 // [1024][24]
    float* shg = sm + 24576;        // [64][26]
    __shared__ float sbh[24];

    const int tid = threadIdx.x;
    const int rg = tid >> 6;        // 0..3 -> rows rg*6 .. rg*6+5
    const int b = tid & 63;         // batch (lanes consecutive -> coalesced ht)
    const int j0 = blockIdx.x * 8;

    // stage Wt (transposed): Wt[k][r] = W_hh[(r/8)*1024 + j0 + (r%8)][k]
    #pragma unroll 1
    for (int it = 0; it < 24; it++) {
        int f4 = tid + it * 256;          // 0..6143
        int r = f4 >> 8;                  // 0..23
        int kq = (f4 & 255) << 2;         // 0..1020
        int grow = (r >> 3) * 1024 + j0 + (r & 7);
        float4 v = *reinterpret_cast<const float4*>(W_hh + (size_t)grow * 1024 + kq);
        Wt[(kq + 0) * 24 + r] = v.x;
        Wt[(kq + 1) * 24 + r] = v.y;
        Wt[(kq + 2) * 24 + r] = v.z;
        Wt[(kq + 3) * 24 + r] = v.w;
    }
    if (tid < 24) sbh[tid] = b_hh[(tid >> 3) * 1024 + j0 + (tid & 7)];

    // init transposed h ping-pong slice for this block's 8 units
    #pragma unroll
    for (int i = 0; i < 2; i++) {
        int idx = tid + i * 256;          // 0..511
        int u = idx >> 6, bb = idx & 63;
        g_ht[0][(j0 + u) * 64 + bb] = hidden[(size_t)bb * 1024 + j0 + u];
    }
    __syncthreads();
    gridbar();    // all blocks' ht[0] slices visible

    for (int t = 0; t < 256; t++) {
        const float* hs = g_ht[t & 1];
        float* hn = g_ht[(t + 1) & 1];

        // prefetch gate-phase operands (independent of the dot loop)
        float xgv[2][3], hold[2];
        int us[2], bs2[2];
        #pragma unroll
        for (int i = 0; i < 2; i++) {
            int idx = tid + i * 256;
            int u = idx >> 6, bb = idx & 63;
            us[i] = u; bs2[i] = bb;
            const float* xp = xg + (size_t)(bb * 256 + t) * 3072 + j0 + u;
            xgv[i][0] = xp[0];
            xgv[i][1] = xp[1024];
            xgv[i][2] = xp[2048];
            hold[i] = hs[(j0 + u) * 64 + bb];
        }

        // 1024-k dot: 3 row-pairs per thread
        uint64_t acc0 = 0ull, acc1 = 0ull, acc2v = 0ull;
        const int r6 = rg * 6;
        #pragma unroll 8
        for (int k = 0; k < 1024; k++) {
            float hv = hs[k * 64 + b];
            uint64_t a2 = pack2(hv, hv);
            const float* wk = Wt + k * 24 + r6;
            uint64_t w0 = *reinterpret_cast<const uint64_t*>(wk);
            uint64_t w1 = *reinterpret_cast<const uint64_t*>(wk + 2);
            uint64_t w2 = *reinterpret_cast<const uint64_t*>(wk + 4);
            acc0 = ffma2(a2, w0, acc0);
            acc1 = ffma2(a2, w1, acc1);
            acc2v = ffma2(a2, w2, acc2v);
        }
        {
            float v0, v1, v2, v3, v4, v5;
            unpack2(acc0, v0, v1);
            unpack2(acc1, v2, v3);
            unpack2(acc2v, v4, v5);
            float* sr = shg + b * 26 + r6;
            sr[0] = v0; sr[1] = v1; sr[2] = v2; sr[3] = v3; sr[4] = v4; sr[5] = v5;
        }
        __syncthreads();

        // gates: 2 (b,u) pairs per thread
        #pragma unroll
        for (int i = 0; i < 2; i++) {
            int u = us[i], bb = bs2[i];
            float hr = shg[bb * 26 + u] + sbh[u];
            float hz = shg[bb * 26 + 8 + u] + sbh[8 + u];
            float hnv = shg[bb * 26 + 16 + u] + sbh[16 + u];
            float r = 1.f / (1.f + expf(-(xgv[i][0] + hr)));
            float z = 1.f / (1.f + expf(-(xgv[i][1] + hz)));
            float n = tanhf(xgv[i][2] + r * hnv);
            float hnew = (1.f - z) * n + z * hold[i];
            hn[(j0 + u) * 64 + bb] = hnew;
            if (t == 255) hfin[(size_t)bb * 1024 + j0 + u] = hnew;
        }
        gridbar();
    }
}

// =====================================================================
// launch
// =====================================================================
extern "C" void kernel_launch(void* const* d_in, const int* in_sizes, int n_in,
                              void* d_out, int out_size)
{
    const float* inp    = (const float*)d_in[0];
    const float* hidden = (const float*)d_in[1];
    const float* W_in   = (const float*)d_in[2];
    const float* b_in   = (const float*)d_in[3];
    const float* W_ih   = (const float*)d_in[4];
    const float* b_ih   = (const float*)d_in[5];
    const float* W_hh   = (const float*)d_in[6];
    const float* b_hh   = (const float*)d_in[7];
    const float* W_out  = (const float*)d_in[8];
    const float* b_out  = (const float*)d_in[9];
    float* out = (float*)d_out;

    cudaFuncSetAttribute(gru_f2_k, cudaFuncAttributeMaxDynamicSharedMemorySize, GRU_SMEM);

    // W_in^T
    transpose_k<<<dim3(32, 32), dim3(32, 8)>>>(W_in, g_wt);
    // b_comb = W_ih @ b_in + b_ih
    bcomb_k<<<12, 256>>>(W_ih, b_in, b_ih, g_bcomb);
    // W_comb = W_ih @ W_in          (M=3072, N=1024, K=1024)
    gemm_f2_k<<<dim3(8, 24), 256>>>(W_ih, g_wt, nullptr, g_wcomb, 3072, 1024, 1024);
    // x_gates = inp @ W_comb^T + b  (M=16384, N=3072, K=1024)
    gemm_f2_k<<<dim3(24, 128), 256>>>(inp, g_wcomb, g_bcomb, g_xg, 16384, 3072, 1024);
    // recurrence (persistent)
    gru_f2_k<<<NBLK2, 256, GRU_SMEM>>>(g_xg, W_hh, b_hh, hidden, g_hfin);
    // out_last = h_T @ W_out^T + b  (M=64, N=1024, K=1024)
    gemm_f2_k<<<dim3(8, 1), 256>>>(g_hfin, W_out, b_out, out, 64, 1024, 1024);
    // hidden_out = h_T
    copy_k<<<256, 256>>>(g_hfin, out + 65536, 65536);
}

// round 9
// speedup vs baseline: 3.1032x; 1.7462x over previous
#include <cuda_runtime.h>
#include <cstdint>
#include <math.h>

#define NBLK2 128

__device__ float g_xg[16384ull * 3072];
__device__ float g_wt[1024 * 1024];
__device__ float g_wcomb[3072 * 1024];
__device__ float g_bcomb[3072];
__device__ float g_hfin[64 * 1024];
__device__ float g_ht[2][1024 * 64];      // transposed hidden ping-pong: [k][b]
__device__ unsigned g_cnt = 0, g_gen = 0;

// ---------------- f32x2 helpers ----------------
__device__ __forceinline__ uint64_t pack2(float lo, float hi) {
    uint64_t r;
    asm("mov.b64 %0, {%1, %2};" : "=l"(r) : "f"(lo), "f"(hi));
    return r;
}
__device__ __forceinline__ void unpack2(uint64_t v, float& lo, float& hi) {
    asm("mov.b64 {%0, %1}, %2;" : "=f"(lo), "=f"(hi) : "l"(v));
}
__device__ __forceinline__ uint64_t ffma2(uint64_t a, uint64_t b, uint64_t c) {
    uint64_t d;
    asm("fma.rn.f32x2 %0, %1, %2, %3;" : "=l"(d) : "l"(a), "l"(b), "l"(c));
    return d;
}

// ---------------- prep kernels ----------------
__global__ void transpose_k(const float* __restrict__ in, float* __restrict__ out) {
    __shared__ float t[32][33];
    int x = blockIdx.x * 32 + threadIdx.x, y = blockIdx.y * 32 + threadIdx.y;
    #pragma unroll
    for (int i = 0; i < 32; i += 8) t[threadIdx.y + i][threadIdx.x] = in[(size_t)(y + i) * 1024 + x];
    __syncthreads();
    int xo = blockIdx.y * 32 + threadIdx.x, yo = blockIdx.x * 32 + threadIdx.y;
    #pragma unroll
    for (int i = 0; i < 32; i += 8) out[(size_t)(yo + i) * 1024 + xo] = t[threadIdx.x][threadIdx.y + i];
}
__global__ void bcomb_k(const float* __restrict__ W, const float* __restrict__ b_in,
                        const float* __restrict__ b_ih, float* __restrict__ out) {
    int g = blockIdx.x * blockDim.x + threadIdx.x;
    if (g < 3072) {
        float s = b_ih[g];
        const float* row = W + (size_t)g * 1024;
        for (int h = 0; h < 1024; h++) s += row[h] * b_in[h];
        out[g] = s;
    }
}
__global__ void copy_k(const float* __restrict__ s, float* __restrict__ d, int n) {
    int i = blockIdx.x * blockDim.x + threadIdx.x;
    if (i < n) d[i] = s[i];
}

// =====================================================================
// SIMT fp32 NT GEMM via fma.rn.f32x2: C[M,N] = A[M,K] @ B[N,K]^T (+bias)
// 256x128 block tile, BK=16, 512 threads (16 warps/SM), 8x8 per thread.
// Dynamic smem, double-buffered. N%128==0, K%16==0; M guarded.
// =====================================================================
#define GEMM_SMEM ((2 * 16 * 260 + 2 * 16 * 132) * 4)   // 50176 bytes
#define AS(b, k, r) sm[((b) * 16 + (k)) * 260 + (r)]
#define BS(b, k, r) sm[8320 + ((b) * 16 + (k)) * 132 + (r)]

__global__ __launch_bounds__(512, 1)
void gemm_f2_k(const float* __restrict__ A, const float* __restrict__ B,
               const float* __restrict__ bias, float* __restrict__ C,
               int M, int N, int K)
{
    extern __shared__ float sm[];
    const int tid = threadIdx.x, tx = tid & 15, ty = tid >> 4;   // ty 0..31
    const int mB = blockIdx.y * 256, nB = blockIdx.x * 128;

    uint64_t acc[8][4];
    #pragma unroll
    for (int i = 0; i < 8; i++)
        #pragma unroll
        for (int j = 0; j < 4; j++) acc[i][j] = 0ull;

    const int NKT = K >> 4;
    // A: 1024 float4/tile (2 per thread); B: 512 float4 (1 per thread)
    int ar[2], ak[2], br, bk;
    #pragma unroll
    for (int i = 0; i < 2; i++) {
        int id = tid + i * 512;
        ar[i] = id >> 2; ak[i] = (id & 3) << 2;
    }
    br = tid >> 2; bk = (tid & 3) << 2;

    float4 ra[2], rb;
    #pragma unroll
    for (int i = 0; i < 2; i++)
        ra[i] = (mB + ar[i] < M) ? *reinterpret_cast<const float4*>(A + (size_t)(mB + ar[i]) * K + ak[i])
                                 : make_float4(0.f, 0.f, 0.f, 0.f);
    rb = *reinterpret_cast<const float4*>(B + (size_t)(nB + br) * K + bk);

    #pragma unroll
    for (int i = 0; i < 2; i++) {
        const float* p = &ra[i].x;
        #pragma unroll
        for (int j = 0; j < 4; j++) AS(0, ak[i] + j, ar[i]) = p[j];
    }
    {
        const float* p = &rb.x;
        #pragma unroll
        for (int j = 0; j < 4; j++) BS(0, bk + j, br) = p[j];
    }
    __syncthreads();

    for (int kt = 0; kt < NKT; kt++) {
        const int b = kt & 1;
        if (kt + 1 < NKT) {
            int k0 = (kt + 1) << 4;
            #pragma unroll
            for (int i = 0; i < 2; i++)
                ra[i] = (mB + ar[i] < M) ? *reinterpret_cast<const float4*>(A + (size_t)(mB + ar[i]) * K + k0 + ak[i])
                                         : make_float4(0.f, 0.f, 0.f, 0.f);
            rb = *reinterpret_cast<const float4*>(B + (size_t)(nB + br) * K + k0 + bk);
        }
        #pragma unroll
        for (int k = 0; k < 16; k++) {
            float4 a0 = *reinterpret_cast<const float4*>(&AS(b, k, ty * 4));
            float4 a1 = *reinterpret_cast<const float4*>(&AS(b, k, 128 + ty * 4));
            float4 b0 = *reinterpret_cast<const float4*>(&BS(b, k, tx * 4));
            float4 b1 = *reinterpret_cast<const float4*>(&BS(b, k, 64 + tx * 4));
            uint64_t bp[4] = { pack2(b0.x, b0.y), pack2(b0.z, b0.w),
                               pack2(b1.x, b1.y), pack2(b1.z, b1.w) };
            float av[8] = { a0.x, a0.y, a0.z, a0.w, a1.x, a1.y, a1.z, a1.w };
            #pragma unroll
            for (int i = 0; i < 8; i++) {
                uint64_t ad = pack2(av[i], av[i]);
                #pragma unroll
                for (int j = 0; j < 4; j++) acc[i][j] = ffma2(ad, bp[j], acc[i][j]);
            }
        }
        if (kt + 1 < NKT) {
            int nb = b ^ 1;
            #pragma unroll
            for (int i = 0; i < 2; i++) {
                const float* p = &ra[i].x;
                #pragma unroll
                for (int j = 0; j < 4; j++) AS(nb, ak[i] + j, ar[i]) = p[j];
            }
            {
                const float* p = &rb.x;
                #pragma unroll
                for (int j = 0; j < 4; j++) BS(nb, bk + j, br) = p[j];
            }
            __syncthreads();
        }
    }

    #pragma unroll
    for (int i = 0; i < 8; i++) {
        int row = mB + ((i < 4) ? ty * 4 + i : 128 + ty * 4 + (i - 4));
        if (row < M) {
            float* cr = C + (size_t)row * N + nB;
            #pragma unroll
            for (int j = 0; j < 4; j++) {
                int c = (j < 2) ? tx * 4 + 2 * j : 64 + tx * 4 + 2 * (j - 2);
                float lo, hi;
                unpack2(acc[i][j], lo, hi);
                cr[c]     = lo + (bias ? bias[nB + c] : 0.f);
                cr[c + 1] = hi + (bias ? bias[nB + c + 1] : 0.f);
            }
        }
    }
}

// =====================================================================
// Persistent SIMT GRU recurrence (fp32, f32x2). 128 blocks x 512 threads.
// Block owns 8 units (24 W rows). Wt[k][24] resident in smem (96KB).
// Warp w: k-slice ks=w>>2 (256 k), row-group rg=w&3 (6 rows).
// Lane owns a batch PAIR: per k = 1 LDG.64 + 3 LDS.64 + 2 pack + 6 FFMA2
// (12 MACs). Partials over 4 k-slices reduced in smem, then fused gates.
// =====================================================================
#define GRU_SMEM (1024 * 24 * 4 + 4 * 64 * 26 * 4)   // 98304 + 26624 = 124928

__device__ __forceinline__ void gridbar() {
    __syncthreads();
    if (threadIdx.x == 0) {
        __threadfence();
        unsigned gen = atomicAdd(&g_gen, 0u);
        if (atomicAdd(&g_cnt, 1u) == NBLK2 - 1u) {
            atomicExch(&g_cnt, 0u);
            __threadfence();
            atomicAdd(&g_gen, 1u);
        } else {
            while (atomicAdd(&g_gen, 0u) == gen) { }
        }
        __threadfence();
    }
    __syncthreads();
}

__global__ __launch_bounds__(512, 1)
void gru_f2_k(const float* __restrict__ xg, const float* __restrict__ W_hh,
              const float* __restrict__ b_hh, const float* __restrict__ hidden,
              float* __restrict__ hfin)
{
    extern __shared__ float sm[];
    float* Wt = sm;                 // [1024][24]
    float* shg = sm + 24576;        // [4][64][26]
    __shared__ float sbh[24];

    const int tid = threadIdx.x;
    const int warp = tid >> 5, lane = tid & 31;
    const int rg = warp & 3, ks = warp >> 2;
    const int r6 = rg * 6, k0 = ks << 8;
    const int j0 = blockIdx.x * 8;
    const int bg = tid >> 3, ug = tid & 7;   // gates mapping: 64 x 8

    // stage Wt (transposed): Wt[k][r] = W_hh[(r/8)*1024 + j0 + (r%8)][k]
    #pragma unroll 1
    for (int it = 0; it < 12; it++) {
        int f4 = tid + it * 512;          // 0..6143
        int r = f4 >> 8;                  // 0..23
        int kq = (f4 & 255) << 2;         // 0..1020
        int grow = (r >> 3) * 1024 + j0 + (r & 7);
        float4 v = *reinterpret_cast<const float4*>(W_hh + (size_t)grow * 1024 + kq);
        Wt[(kq + 0) * 24 + r] = v.x;
        Wt[(kq + 1) * 24 + r] = v.y;
        Wt[(kq + 2) * 24 + r] = v.z;
        Wt[(kq + 3) * 24 + r] = v.w;
    }
    if (tid < 24) sbh[tid] = b_hh[(tid >> 3) * 1024 + j0 + (tid & 7)];

    // init transposed h slice for this block's 8 units (512 = 8*64 exactly)
    g_ht[0][(j0 + ug) * 64 + bg] = hidden[(size_t)bg * 1024 + j0 + ug];
    __syncthreads();
    gridbar();

    for (int t = 0; t < 256; t++) {
        const float* hs = g_ht[t & 1];
        float* hnx = g_ht[(t + 1) & 1];

        // prefetch gates operands (independent of dot loop)
        float xrv, xzv, xnv, hold;
        {
            const float* xp = xg + (size_t)(bg * 256 + t) * 3072 + j0 + ug;
            xrv = xp[0]; xzv = xp[1024]; xnv = xp[2048];
            hold = hs[(j0 + ug) * 64 + bg];
        }

        // dot over this warp's k-slice; lane handles batches 2*lane, 2*lane+1
        uint64_t a0 = 0ull, a1 = 0ull, a2 = 0ull, c0 = 0ull, c1 = 0ull, c2 = 0ull;
        const float* hp = hs + 2 * lane;
        #pragma unroll 8
        for (int k = k0; k < k0 + 256; k++) {
            float2 hv = *reinterpret_cast<const float2*>(hp + k * 64);
            uint64_t d0 = pack2(hv.x, hv.x);
            uint64_t d1 = pack2(hv.y, hv.y);
            const float* wk = Wt + k * 24 + r6;
            uint64_t w0 = *reinterpret_cast<const uint64_t*>(wk);
            uint64_t w1 = *reinterpret_cast<const uint64_t*>(wk + 2);
            uint64_t w2 = *reinterpret_cast<const uint64_t*>(wk + 4);
            a0 = ffma2(d0, w0, a0); a1 = ffma2(d0, w1, a1); a2 = ffma2(d0, w2, a2);
            c0 = ffma2(d1, w0, c0); c1 = ffma2(d1, w1, c1); c2 = ffma2(d1, w2, c2);
        }
        {
            float v0, v1, v2, v3, v4, v5;
            float* p = shg + (size_t)(ks * 64 + 2 * lane) * 26 + r6;
            unpack2(a0, v0, v1); unpack2(a1, v2, v3); unpack2(a2, v4, v5);
            p[0] = v0; p[1] = v1; p[2] = v2; p[3] = v3; p[4] = v4; p[5] = v5;
            p += 26;
            unpack2(c0, v0, v1); unpack2(c1, v2, v3); unpack2(c2, v4, v5);
            p[0] = v0; p[1] = v1; p[2] = v2; p[3] = v3; p[4] = v4; p[5] = v5;
        }
        __syncthreads();

        // reduce 4 k-slices + fused gates: thread = (bg, ug)
        {
            float hr = 0.f, hz = 0.f, hn2 = 0.f;
            #pragma unroll
            for (int s = 0; s < 4; s++) {
                const float* base = shg + (size_t)(s * 64 + bg) * 26;
                hr  += base[ug];
                hz  += base[8 + ug];
                hn2 += base[16 + ug];
            }
            float r = 1.f / (1.f + expf(-(xrv + hr + sbh[ug])));
            float z = 1.f / (1.f + expf(-(xzv + hz + sbh[8 + ug])));
            float n = tanhf(xnv + r * (hn2 + sbh[16 + ug]));
            float hnew = (1.f - z) * n + z * hold;
            hnx[(j0 + ug) * 64 + bg] = hnew;
            if (t == 255) hfin[(size_t)bg * 1024 + j0 + ug] = hnew;
        }
        gridbar();
    }
}

// =====================================================================
// launch
// =====================================================================
extern "C" void kernel_launch(void* const* d_in, const int* in_sizes, int n_in,
                              void* d_out, int out_size)
{
    const float* inp    = (const float*)d_in[0];
    const float* hidden = (const float*)d_in[1];
    const float* W_in   = (const float*)d_in[2];
    const float* b_in   = (const float*)d_in[3];
    const float* W_ih   = (const float*)d_in[4];
    const float* b_ih   = (const float*)d_in[5];
    const float* W_hh   = (const float*)d_in[6];
    const float* b_hh   = (const float*)d_in[7];
    const float* W_out  = (const float*)d_in[8];
    const float* b_out  = (const float*)d_in[9];
    float* out = (float*)d_out;

    cudaFuncSetAttribute(gemm_f2_k, cudaFuncAttributeMaxDynamicSharedMemorySize, GEMM_SMEM);
    cudaFuncSetAttribute(gru_f2_k, cudaFuncAttributeMaxDynamicSharedMemorySize, GRU_SMEM);

    // W_in^T
    transpose_k<<<dim3(32, 32), dim3(32, 8)>>>(W_in, g_wt);
    // b_comb = W_ih @ b_in + b_ih
    bcomb_k<<<12, 256>>>(W_ih, b_in, b_ih, g_bcomb);
    // W_comb = W_ih @ W_in          (M=3072, N=1024, K=1024)
    gemm_f2_k<<<dim3(8, 12), 512, GEMM_SMEM>>>(W_ih, g_wt, nullptr, g_wcomb, 3072, 1024, 1024);
    // x_gates = inp @ W_comb^T + b  (M=16384, N=3072, K=1024)
    gemm_f2_k<<<dim3(24, 64), 512, GEMM_SMEM>>>(inp, g_wcomb, g_bcomb, g_xg, 16384, 3072, 1024);
    // recurrence (persistent)
    gru_f2_k<<<NBLK2, 512, GRU_SMEM>>>(g_xg, W_hh, b_hh, hidden, g_hfin);
    // out_last = h_T @ W_out^T + b  (M=64, N=1024, K=1024)
    gemm_f2_k<<<dim3(8, 1), 512, GEMM_SMEM>>>(g_hfin, W_out, b_out, out, 64, 1024, 1024);
    // hidden_out = h_T
    copy_k<<<256, 256>>>(g_hfin, out + 65536, 65536);
}